// round 10
// baseline (speedup 1.0000x reference)
#include <cuda_runtime.h>
#include <cstdint>

// OneHotEncoder: per-row token histogram (skip pad_idx=0) -> float counts.
// tokens: [B, T] int32, out: [B, 32000] float32.
//
// R10: the smem-atomic family is floor-bound by ATOMS lane throughput
// (~10us invariant across R4-R9). Move the RMW to the L2 atomic ALUs
// (184 LTS partitions, spread REDG ~3K cyc chip for 524K ops):
//   K1: zero the output via TMA bulk stores from a zeroed smem buffer
//       (allocates lines in L2, LSU-free; ~2.7us at the LTS store cap).
//   K2: single-pass scatter: one int4 of tokens per thread, predicated
//       RED.E.ADD.F32 (+1.0f) into the L2-resident output. No redundant
//       x8 scan -> not issue-bound; no smem atomics -> no ATOMS floor.
// fp32 adds of integer counts are exact. Column 0 stays zero (pads skipped).

constexpr int VOCAB      = 32000;
constexpr int NT_ZERO    = 256;
constexpr int NT_SCATTER = 256;
constexpr int ZCHUNK     = 4000;                  // floats per TMA store (16000B)
constexpr int ZSTORES    = VOCAB / ZCHUNK;        // 8 per row

__global__ __launch_bounds__(NT_ZERO)
void onehot_zero_tma_kernel(float* __restrict__ out)
{
    __shared__ __align__(16) float zbuf[ZCHUNK];  // 16000 B of zeroes

    const int b   = blockIdx.x;
    const int tid = threadIdx.x;

    float4 z = make_float4(0.f, 0.f, 0.f, 0.f);
    #pragma unroll
    for (int i = tid; i < ZCHUNK / 4; i += NT_ZERO) {
        reinterpret_cast<float4*>(zbuf)[i] = z;
    }
    __syncthreads();

    if (tid == 0) {
        asm volatile("fence.proxy.async.shared::cta;" ::: "memory");
        uint32_t saddr = (uint32_t)__cvta_generic_to_shared(zbuf);
        float* rowbase = out + (size_t)b * VOCAB;
        #pragma unroll
        for (int k = 0; k < ZSTORES; k++) {
            asm volatile(
                "cp.async.bulk.global.shared::cta.bulk_group [%0], [%1], %2;"
                :: "l"(rowbase + k * ZCHUNK), "r"(saddr),
                   "r"((unsigned)(ZCHUNK * sizeof(float)))
                : "memory");
        }
        asm volatile("cp.async.bulk.commit_group;" ::: "memory");
        asm volatile("cp.async.bulk.wait_group 0;" ::: "memory");
    }
}

__global__ __launch_bounds__(NT_SCATTER, 8)
void onehot_scatter_kernel(const int4* __restrict__ tokens4,
                           float* __restrict__ out,
                           int vecs_per_row)   // T/4 = 512
{
    const int g = blockIdx.x * NT_SCATTER + threadIdx.x;
    const int b = g / vecs_per_row;

    int4 t = tokens4[g];
    float* __restrict__ orow = out + (size_t)b * VOCAB;

    // atomicAdd with unused result lowers to RED.E.ADD.F32 (no return trip).
    if (t.x != 0) atomicAdd(&orow[t.x], 1.0f);
    if (t.y != 0) atomicAdd(&orow[t.y], 1.0f);
    if (t.z != 0) atomicAdd(&orow[t.z], 1.0f);
    if (t.w != 0) atomicAdd(&orow[t.w], 1.0f);
}

extern "C" void kernel_launch(void* const* d_in, const int* in_sizes, int n_in,
                              void* d_out, int out_size)
{
    const int* tokens = (const int*)d_in[0];   // [B, T] int32
    // d_in[1] = lengths [B] int32 — unused by the reference computation.

    const int B = in_sizes[1];                 // 256
    const int T = in_sizes[0] / B;             // 2048

    float* out = (float*)d_out;                // [B, VOCAB] float32

    // K1: TMA-zero the whole output (L2-allocating).
    onehot_zero_tma_kernel<<<B, NT_ZERO>>>(out);

    // K2: single-pass L2 scatter-add (same-stream launch orders after K1).
    const int total_vecs = (B * T) / 4;        // 131072
    const int blocks = total_vecs / NT_SCATTER;
    onehot_scatter_kernel<<<blocks, NT_SCATTER>>>(
        (const int4*)tokens, out, T / 4);
}

// round 11
// speedup vs baseline: 1.4060x; 1.4060x over previous
#include <cuda_runtime.h>
#include <cstdint>

// OneHotEncoder: per-row token histogram (skip pad_idx=0) -> float counts.
// tokens: [B, T] int32, out: [B, 32000] float32.
//
// R11: discriminate f32-vs-u32 smem atomic cost. All f32-hist variants
// (R4-R9) pinned at ~10us; R2 (u32 packed-u16 atomics) hit 9.4us despite a
// much worse structure -> hypothesis: ATOMS.ADD.F32 ~4cyc/lane vs u32
// ~2cyc/lane. This kernel = R7's proven skeleton (SPLIT=8, 256thr, token
// register prefetch, pad-fold range check, TMA bulk store) with the hist as
// u16 PAIRS packed in u32 words (counts <= 2048 < 2^16; low-half +1 can't
// carry -> atomicAdd(u32, 1<<16*(bin&1)) exact), plus a short u16->f32
// convert pass into a separate smem buffer that TMA stores.
// Column 0 stays zero (pad tokens excluded by the folded range check).

constexpr int VOCAB    = 32000;
constexpr int SPLIT    = 8;
constexpr int BINS     = VOCAB / SPLIT;     // 4000 bins per slice
constexpr int HWORDS   = BINS / 2;          // 2000 packed u32 words (8000B)
constexpr int NTHREADS = 256;
constexpr int VPT      = 2;                 // int4 per thread (T=2048)

__global__ __launch_bounds__(NTHREADS)
void onehot_hist_u16_tma_kernel(const int4* __restrict__ tokens4,
                                float* __restrict__ out,
                                int vecs_per_row)   // T/4 = 512
{
    // [0, HWORDS): packed u16-pair histogram. Then f32 staging buffer.
    extern __shared__ unsigned int smem_raw[];
    unsigned int* hist = smem_raw;                        // 8000 B
    float*        fbuf = (float*)(smem_raw + HWORDS);     // 16000 B

    const int cta = blockIdx.x;
    const int s   = cta & (SPLIT - 1);       // vocab slice index
    const int b   = cta >> 3;                // row index
    const int lo  = s * BINS;
    const int tid = threadIdx.x;

    // Pad-fold: on slice 0 shift the window by 1 so t==0 fails the single
    // unsigned range check. bin = (t - loAdj) + adj.
    const int      adj   = (s == 0) ? 1 : 0;
    const int      loAdj = lo + adj;
    const unsigned range = (unsigned)(BINS - adj);

    // Front-batched token prefetch (2 x LDG.128) to hide L2 latency behind
    // the zero loop.
    const int4* __restrict__ trow = tokens4 + (size_t)b * vecs_per_row;
    int4 tv[VPT];
    #pragma unroll
    for (int v = 0; v < VPT; v++) {
        tv[v] = trow[tid + v * NTHREADS];
    }

    // Zero the packed histogram (500 uint4 over 256 threads).
    uint4 z = make_uint4(0u, 0u, 0u, 0u);
    #pragma unroll
    for (int i = tid; i < HWORDS / 4; i += NTHREADS) {
        reinterpret_cast<uint4*>(hist)[i] = z;
    }
    __syncthreads();

    // Count: sub + unsigned cmp, then predicated u32 ATOMS on the packed word.
    #pragma unroll
    for (int v = 0; v < VPT; v++) {
        int4 t = tv[v];
        unsigned x;
        x = (unsigned)(t.x - loAdj);
        if (x < range) { unsigned bin = x + adj; atomicAdd(&hist[bin >> 1], 1u << ((bin & 1u) << 4)); }
        x = (unsigned)(t.y - loAdj);
        if (x < range) { unsigned bin = x + adj; atomicAdd(&hist[bin >> 1], 1u << ((bin & 1u) << 4)); }
        x = (unsigned)(t.z - loAdj);
        if (x < range) { unsigned bin = x + adj; atomicAdd(&hist[bin >> 1], 1u << ((bin & 1u) << 4)); }
        x = (unsigned)(t.w - loAdj);
        if (x < range) { unsigned bin = x + adj; atomicAdd(&hist[bin >> 1], 1u << ((bin & 1u) << 4)); }
    }
    __syncthreads();

    // Convert packed u16 pairs -> f32 staging buffer (float2 stores).
    #pragma unroll
    for (int i = tid; i < HWORDS; i += NTHREADS) {
        unsigned w = hist[i];
        float2 f;
        f.x = (float)(w & 0xFFFFu);
        f.y = (float)(w >> 16);
        reinterpret_cast<float2*>(fbuf)[i] = f;
    }
    __syncthreads();

    // One TMA 1-D bulk store writes the 16000B f32 slice to global.
    if (tid == 0) {
        asm volatile("fence.proxy.async.shared::cta;" ::: "memory");
        uint32_t saddr = (uint32_t)__cvta_generic_to_shared(fbuf);
        float* gdst = out + (size_t)b * VOCAB + lo;   // 16B-aligned slices
        asm volatile(
            "cp.async.bulk.global.shared::cta.bulk_group [%0], [%1], %2;"
            :: "l"(gdst), "r"(saddr), "r"((unsigned)(BINS * sizeof(float)))
            : "memory");
        asm volatile("cp.async.bulk.commit_group;" ::: "memory");
        asm volatile("cp.async.bulk.wait_group 0;" ::: "memory");
    }
}

extern "C" void kernel_launch(void* const* d_in, const int* in_sizes, int n_in,
                              void* d_out, int out_size)
{
    const int* tokens = (const int*)d_in[0];   // [B, T] int32
    // d_in[1] = lengths [B] int32 — unused by the reference computation.

    const int B = in_sizes[1];                 // 256
    const int T = in_sizes[0] / B;             // 2048

    float* out = (float*)d_out;                // [B, VOCAB] float32

    const int smem_bytes = HWORDS * 4 + BINS * 4;   // 8000 + 16000 = 24000
    cudaFuncSetAttribute(onehot_hist_u16_tma_kernel,
                         cudaFuncAttributeMaxDynamicSharedMemorySize,
                         smem_bytes);
    cudaFuncSetAttribute(onehot_hist_u16_tma_kernel,
                         cudaFuncAttributePreferredSharedMemoryCarveout,
                         cudaSharedmemCarveoutMaxShared);

    onehot_hist_u16_tma_kernel<<<B * SPLIT, NTHREADS, smem_bytes>>>(
        (const int4*)tokens, out, T / 4);
}